// round 5
// baseline (speedup 1.0000x reference)
#include <cuda_runtime.h>

// VolSDF volume renderer.
// Inputs: distance [M,128,1] f32, color [M,128,3] f32, depth_values [M,128] f32
// Output: out_color [M,3] f32 followed by geometry [M,3] f32 (zeros).
//
// One warp per ray; lane l owns samples [4l, 4l+4). Sample 127 carries the
// FAR_DELTA=1e10 sentinel, so sigma_delta[127] ~ 1e8..1e11 and the reference's
// float32 cumsum determines T[127] in {~0, 1} purely by rounding. Error
// algebra across previous rounds shows the reference behaves like a BLOCKED
// scan (chunk=16): cs127 = fl( S[0:112) + fl( S[112:127) + sd127 ) ), i.e. the
// local chunk prefix is absorbed first (rounds away), then the chunk-exclusive
// prefix is added as ONE piece. We replicate exactly that for sample 127.

#define FAR_DELTA_ 1e10f

__device__ __forceinline__ float sdf_density(float d) {
    float s = -d;
    // match reference rounding: exp(±|s|/0.05f) with true division by fl(0.05)
    float a = fabsf(s) / 0.05f;
    float e = expf(-a);
    return (s <= 0.0f) ? __fmul_rn(10.0f, __fmul_rn(0.5f, e))
                       : __fmul_rn(10.0f, __fsub_rn(1.0f, __fmul_rn(0.5f, e)));
}

// One render step with reference f32 rounding:
//   inc = fl(run + sd); T = exp(-(inc - sd)); w = T*(1-exp(-sd)); run = inc
__device__ __forceinline__ void render_step(float& run, float sd,
                                            float cr, float cg, float cb,
                                            float& r, float& g, float& b) {
    float inc = __fadd_rn(run, sd);
    float T   = expf(-__fsub_rn(inc, sd));
    float w   = T * (1.0f - expf(-sd));
    run = inc;
    r += w * cr; g += w * cg; b += w * cb;
}

__global__ void __launch_bounds__(256) volsdf_render_kernel(
    const float* __restrict__ dist,
    const float* __restrict__ color,
    const float* __restrict__ depth,
    float* __restrict__ out,
    int M)
{
    const int gtid = blockIdx.x * blockDim.x + threadIdx.x;
    const int ray  = gtid >> 5;
    const int lane = gtid & 31;
    if (ray >= M) return;

    const unsigned FULL = 0xffffffffu;
    const long long base = (long long)ray * 128;

    // ---- coalesced vector loads: 4 samples per lane ----
    const float4 d4 = *reinterpret_cast<const float4*>(dist  + base + lane * 4);
    const float4 z4 = *reinterpret_cast<const float4*>(depth + base + lane * 4);

    const long long cbase = base * 3 + (long long)lane * 12;
    const float4 c0 = *reinterpret_cast<const float4*>(color + cbase + 0);
    const float4 c1 = *reinterpret_cast<const float4*>(color + cbase + 4);
    const float4 c2 = *reinterpret_cast<const float4*>(color + cbase + 8);

    // next lane's first depth (delta for this lane's last sample)
    const float z_next = __shfl_down_sync(FULL, z4.x, 1);

    const float del0 = __fsub_rn(z4.y, z4.x);
    const float del1 = __fsub_rn(z4.z, z4.y);
    const float del2 = __fsub_rn(z4.w, z4.z);
    const float del3 = (lane == 31) ? FAR_DELTA_ : __fsub_rn(z_next, z4.w);

    const float sd0 = __fmul_rn(sdf_density(d4.x), del0);
    const float sd1 = __fmul_rn(sdf_density(d4.y), del1);
    const float sd2 = __fmul_rn(sdf_density(d4.z), del2);
    const float sd3 = __fmul_rn(sdf_density(d4.w), del3);

    const float lsum = __fadd_rn(__fadd_rn(__fadd_rn(sd0, sd1), sd2), sd3);

    // warp inclusive scan of per-lane sums (Kogge-Stone)
    float x = lsum;
    #pragma unroll
    for (int off = 1; off < 32; off <<= 1) {
        float y = __shfl_up_sync(FULL, x, off);
        if (lane >= off) x += y;
    }
    // exclusive prefix via shfl (no subtraction: lane 31's lsum is ~1e11)
    float run = __shfl_up_sync(FULL, x, 1);
    if (lane == 0) run = 0.0f;

    // snapshots for the sample-127 blocked-scan combine (uniform execution)
    const float x27 = __shfl_sync(FULL, x, 27);   // S[0:112)
    const float x30 = __shfl_sync(FULL, x, 30);   // S[0:124)

    float r = 0.0f, g = 0.0f, b = 0.0f;
    render_step(run, sd0, c0.x, c0.y, c0.z, r, g, b);
    render_step(run, sd1, c0.w, c1.x, c1.y, r, g, b);
    render_step(run, sd2, c1.z, c1.w, c2.x, r, g, b);

    if (lane != 31) {
        render_step(run, sd3, c2.y, c2.z, c2.w, r, g, b);
    } else {
        // Blocked scan, chunk 16: local chunk covers samples [112,128).
        //   Lloc  = S[112:127)  (small, ~3.5)
        //   local = fl(Lloc + sd127)        -> Lloc rounds away vs huge sd127
        //   cs127 = fl(S[0:112) + local)    -> prefix added as ONE piece
        //   q     = fl(cs127 - sd127); T = exp(-q)
        const float Lloc  = __fadd_rn(__fsub_rn(x30, x27),
                                      __fadd_rn(__fadd_rn(sd0, sd1), sd2));
        const float local = __fadd_rn(Lloc, sd3);
        const float cs    = __fadd_rn(x27, local);
        const float q     = __fsub_rn(cs, sd3);
        const float T     = expf(-q);
        const float w     = T * (1.0f - expf(-sd3));
        r += w * c2.y; g += w * c2.z; b += w * c2.w;
    }

    // warp reduction of RGB
    #pragma unroll
    for (int off = 16; off > 0; off >>= 1) {
        r += __shfl_xor_sync(FULL, r, off);
        g += __shfl_xor_sync(FULL, g, off);
        b += __shfl_xor_sync(FULL, b, off);
    }

    if (lane == 0) {
        out[(long long)ray * 3 + 0] = r;
        out[(long long)ray * 3 + 1] = g;
        out[(long long)ray * 3 + 2] = b;
    }
}

extern "C" void kernel_launch(void* const* d_in, const int* in_sizes, int n_in,
                              void* d_out, int out_size) {
    const float* dist  = (const float*)d_in[0];   // [M,128,1]
    const float* color = (const float*)d_in[1];   // [M,128,3]
    const float* depth = (const float*)d_in[2];   // [M,128]

    const int M = in_sizes[2] / 128;
    float* out = (float*)d_out;

    // geometry output = zeros
    const long long color_elems = (long long)M * 3;
    if ((long long)out_size > color_elems) {
        cudaMemsetAsync(out + color_elems, 0,
                        ((long long)out_size - color_elems) * sizeof(float), 0);
    }

    const int threads = 256;              // 8 warps -> 8 rays per block
    const int blocks  = (M + 7) / 8;
    volsdf_render_kernel<<<blocks, threads>>>(dist, color, depth, out, M);
}

// round 6
// speedup vs baseline: 1.0685x; 1.0685x over previous
#include <cuda_runtime.h>

// VolSDF volume renderer.
// Inputs: distance [M,128,1] f32, color [M,128,3] f32, depth_values [M,128] f32
// Output: out_color [M,3] f32 followed by geometry [M,3] f32 (zeros).
//
// One warp per ray; lane l owns samples [4l, 4l+4). Sample 127 carries the
// FAR_DELTA=1e10 sentinel; the reference's float32 cumsum is a BLOCKED scan
// (chunk=16): cs127 = fl( S[0:112) + fl( S[112:127) + sd127 ) ). We replicate
// exactly that combine for sample 127 (validated: rel_err 8e-8 in R5).
//
// Geometry zeros are written by the kernel itself (lane 1) — no memset node.

#define FAR_DELTA_ 1e10f

__device__ __forceinline__ float sdf_density(float d) {
    float s = -d;
    float a = fabsf(s) / 0.05f;
    float e = expf(-a);
    return (s <= 0.0f) ? __fmul_rn(10.0f, __fmul_rn(0.5f, e))
                       : __fmul_rn(10.0f, __fsub_rn(1.0f, __fmul_rn(0.5f, e)));
}

// One render step with reference f32 rounding:
//   inc = fl(run + sd); T = exp(-(inc - sd)); w = T*(1-exp(-sd)); run = inc
__device__ __forceinline__ void render_step(float& run, float sd,
                                            float cr, float cg, float cb,
                                            float& r, float& g, float& b) {
    float inc = __fadd_rn(run, sd);
    float T   = expf(-__fsub_rn(inc, sd));
    float w   = T * (1.0f - expf(-sd));
    run = inc;
    r += w * cr; g += w * cg; b += w * cb;
}

__device__ __forceinline__ float4 ldcs4(const float* p) {
    return __ldcs(reinterpret_cast<const float4*>(p));
}

__global__ void __launch_bounds__(256, 7) volsdf_render_kernel(
    const float* __restrict__ dist,
    const float* __restrict__ color,
    const float* __restrict__ depth,
    float* __restrict__ out,
    int M)
{
    const int gtid = blockIdx.x * blockDim.x + threadIdx.x;
    const int ray  = gtid >> 5;
    const int lane = gtid & 31;
    if (ray >= M) return;

    const unsigned FULL = 0xffffffffu;
    const long long base = (long long)ray * 128;

    // ---- coalesced streaming vector loads: 4 samples per lane ----
    const float4 d4 = ldcs4(dist  + base + lane * 4);
    const float4 z4 = ldcs4(depth + base + lane * 4);

    const long long cbase = base * 3 + (long long)lane * 12;
    const float4 c0 = ldcs4(color + cbase + 0);
    const float4 c1 = ldcs4(color + cbase + 4);
    const float4 c2 = ldcs4(color + cbase + 8);

    // geometry output zeros (second half of out), written while loads land
    if (lane == 1) {
        const long long gb = (long long)M * 3 + (long long)ray * 3;
        out[gb + 0] = 0.0f; out[gb + 1] = 0.0f; out[gb + 2] = 0.0f;
    }

    // next lane's first depth (delta for this lane's last sample)
    const float z_next = __shfl_down_sync(FULL, z4.x, 1);

    const float del0 = __fsub_rn(z4.y, z4.x);
    const float del1 = __fsub_rn(z4.z, z4.y);
    const float del2 = __fsub_rn(z4.w, z4.z);
    const float del3 = (lane == 31) ? FAR_DELTA_ : __fsub_rn(z_next, z4.w);

    const float sd0 = __fmul_rn(sdf_density(d4.x), del0);
    const float sd1 = __fmul_rn(sdf_density(d4.y), del1);
    const float sd2 = __fmul_rn(sdf_density(d4.z), del2);
    const float sd3 = __fmul_rn(sdf_density(d4.w), del3);

    const float lsum = __fadd_rn(__fadd_rn(__fadd_rn(sd0, sd1), sd2), sd3);

    // warp inclusive scan of per-lane sums (Kogge-Stone)
    float x = lsum;
    #pragma unroll
    for (int off = 1; off < 32; off <<= 1) {
        float y = __shfl_up_sync(FULL, x, off);
        if (lane >= off) x += y;
    }
    // exclusive prefix via shfl (no subtraction: lane 31's lsum is ~1e11)
    float run = __shfl_up_sync(FULL, x, 1);
    if (lane == 0) run = 0.0f;

    // snapshots for the sample-127 blocked-scan combine (uniform execution)
    const float x27 = __shfl_sync(FULL, x, 27);   // S[0:112)
    const float x30 = __shfl_sync(FULL, x, 30);   // S[0:124)

    float r = 0.0f, g = 0.0f, b = 0.0f;
    render_step(run, sd0, c0.x, c0.y, c0.z, r, g, b);
    render_step(run, sd1, c0.w, c1.x, c1.y, r, g, b);
    render_step(run, sd2, c1.z, c1.w, c2.x, r, g, b);

    if (lane != 31) {
        render_step(run, sd3, c2.y, c2.z, c2.w, r, g, b);
    } else {
        // Blocked scan, chunk 16: local chunk covers samples [112,128).
        const float Lloc  = __fadd_rn(__fsub_rn(x30, x27),
                                      __fadd_rn(__fadd_rn(sd0, sd1), sd2));
        const float local = __fadd_rn(Lloc, sd3);
        const float cs    = __fadd_rn(x27, local);
        const float q     = __fsub_rn(cs, sd3);
        const float T     = expf(-q);
        const float w     = T * (1.0f - expf(-sd3));
        r += w * c2.y; g += w * c2.z; b += w * c2.w;
    }

    // warp reduction of RGB
    #pragma unroll
    for (int off = 16; off > 0; off >>= 1) {
        r += __shfl_xor_sync(FULL, r, off);
        g += __shfl_xor_sync(FULL, g, off);
        b += __shfl_xor_sync(FULL, b, off);
    }

    if (lane == 0) {
        const long long ob = (long long)ray * 3;
        out[ob + 0] = r;
        out[ob + 1] = g;
        out[ob + 2] = b;
    }
}

extern "C" void kernel_launch(void* const* d_in, const int* in_sizes, int n_in,
                              void* d_out, int out_size) {
    const float* dist  = (const float*)d_in[0];   // [M,128,1]
    const float* color = (const float*)d_in[1];   // [M,128,3]
    const float* depth = (const float*)d_in[2];   // [M,128]

    const int M = in_sizes[2] / 128;
    float* out = (float*)d_out;

    // Kernel writes out_color and geometry zeros. Only memset anything beyond
    // the expected 6*M elements (normally none).
    const long long expected = (long long)M * 6;
    if ((long long)out_size > expected) {
        cudaMemsetAsync(out + expected, 0,
                        ((long long)out_size - expected) * sizeof(float), 0);
    }

    const int threads = 256;              // 8 warps -> 8 rays per block
    const int blocks  = (M + 7) / 8;
    volsdf_render_kernel<<<blocks, threads>>>(dist, color, depth, out, M);
}